// round 14
// baseline (speedup 1.0000x reference)
#include <cuda_runtime.h>
#include <cuda_bf16.h>
#include <math.h>
#include <cstdint>

#define N_NODES 2000000
#define N_DAGS  20000
#define N_OBS   1000
#define N_TILES (N_NODES / 128)   // 15625
#define FLT_NEG (-3.402823466e+38f)

// ---------------- device scratch ----------------
__device__ int      g_dag_off[N_DAGS + 1];
__device__ int      g_obs_off[N_OBS + 1];
__device__ __align__(16) float g_dagc[N_DAGS * 32];
__device__ __align__(16) float g_globc[N_OBS * 32];
__device__ __align__(16) uint32_t g_seg[N_NODES];
__device__ float    g_cta_m[1024];
__device__ float    g_cta_s[1024];
__device__ int      g_mask_mode;

// ---------------- helpers ----------------
__device__ __forceinline__ uint32_t bf2(float lo, float hi) {
    uint32_t r;
    asm("cvt.rn.bf16x2.f32 %0, %1, %2;" : "=r"(r) : "f"(hi), "f"(lo));
    return r;
}
__device__ __forceinline__ void split2(float2 v, uint32_t& h, uint32_t& l) {
    h = bf2(v.x, v.y);
    float h0 = __uint_as_float(h << 16);
    float h1 = __uint_as_float(h & 0xFFFF0000u);
    l = bf2(v.x - h0, v.y - h1);
}
__device__ __forceinline__ void pf_l2(const void* p) {
    asm volatile("prefetch.global.L2 [%0];" :: "l"(p));
}

#define MMA_BF16(d, a0, a1, a2, a3, b0, b1) \
    asm volatile("mma.sync.aligned.m16n8k16.row.col.f32.bf16.bf16.f32 " \
        "{%0,%1,%2,%3}, {%4,%5,%6,%7}, {%8,%9}, {%0,%1,%2,%3};" \
        : "+f"((d)[0]), "+f"((d)[1]), "+f"((d)[2]), "+f"((d)[3]) \
        : "r"(a0), "r"(a1), "r"(a2), "r"(a3), "r"(b0), "r"(b1))

__device__ __forceinline__ float wp_elem(const float* W1, int k, int col) {
    if (k < 32) return __ldg(W1 + (5 + k) * 32 + col);
    if (k < 37) return __ldg(W1 + (k - 32) * 32 + col);
    return 0.f;
}
__device__ __forceinline__ void w1pair(const float* W1, int k, int col, uint32_t& h, uint32_t& l) {
    float2 v = make_float2(wp_elem(W1, k, col), wp_elem(W1, k + 1, col));
    split2(v, h, l);
}
// x-pair from a byte pointer to this node's x row
__device__ __forceinline__ float2 xpairp(const char* xr, int c) {
    float2 r = make_float2(0.f, 0.f);
    const float* f = (const float*)xr;
    if (c == 0) { r.x = f[0]; r.y = f[1]; }
    else if (c == 1) { r.x = f[2]; r.y = f[3]; }
    else if (c == 2) { r.x = f[4]; }
    return r;
}
__device__ __forceinline__ void osm_combine(float& m, float& s, float m2, float s2) {
    float mn = fmaxf(m, m2);
    s = s * __expf(m - mn) + s2 * __expf(m2 - mn);
    m = mn;
}

// =================== prep: scans (serial chain) ===================
__device__ void scan_body(const void* counts_raw, int n, int total, int* off) {
    __shared__ long long sbuf[1024];
    __shared__ long long carry;
    __shared__ int mode;
    int tid = threadIdx.x;
    const int* c32 = (const int*)counts_raw;
    long long s = 0;
    for (int i = tid; i < n; i += 1024) s += (long long)c32[i];
    sbuf[tid] = s;
    __syncthreads();
    for (int st = 512; st; st >>= 1) {
        if (tid < st) sbuf[tid] += sbuf[tid + st];
        __syncthreads();
    }
    if (tid == 0) { mode = (sbuf[0] == (long long)total) ? 0 : 1; carry = 0; }
    __syncthreads();
    const long long* c64 = (const long long*)counts_raw;
    for (int base = 0; base < n; base += 1024) {
        int i = base + tid;
        long long v = 0;
        if (i < n) v = (mode == 0) ? (long long)c32[i] : c64[i];
        sbuf[tid] = v;
        __syncthreads();
        for (int st = 1; st < 1024; st <<= 1) {
            long long t = (tid >= st) ? sbuf[tid - st] : 0;
            __syncthreads();
            sbuf[tid] += t;
            __syncthreads();
        }
        long long incl = sbuf[tid];
        if (i < n) off[i] = (int)(carry + incl - v);
        __syncthreads();
        if (tid == 0) carry += sbuf[1023];
        __syncthreads();
    }
    if (tid == 0) off[n] = (int)carry;
}

__global__ void scan_kernel(const void* __restrict__ cnt_dag, const void* __restrict__ cnt_obs) {
    if (blockIdx.x == 0) scan_body(cnt_dag, N_DAGS, N_NODES, g_dag_off);
    else                 scan_body(cnt_obs, N_OBS, N_NODES, g_obs_off);
}

// =================== prep: contrib + mask detect (independent branch) ===================
__global__ void contrib_kernel(const float* __restrict__ dag_sum, const float* __restrict__ glob_sum,
                               const float* __restrict__ W1, const float* __restrict__ b1,
                               const unsigned char* __restrict__ mask) {
    int b = blockIdx.x;
    if (b == 0) {
        // mask dtype detect
        __shared__ int c1, c2;
        if (threadIdx.x == 0) { c1 = 0; c2 = 0; }
        __syncthreads();
        int l1 = 0, l2 = 0;
        for (int i = threadIdx.x; i < 4096; i += blockDim.x) {
            unsigned char bb = mask[i];
            if (bb) { int r = i & 3; if (r == 1) l1++; if (r == 2) l2++; }
        }
        atomicAdd(&c1, l1); atomicAdd(&c2, l2);
        __syncthreads();
        if (threadIdx.x == 0) {
            if (c1 == 0 && c2 == 0)      g_mask_mode = 1;
            else if (c1 == 0 && c2 > 0)  g_mask_mode = 2;
            else                         g_mask_mode = 0;
        }
        return;
    }
    if (b <= 625) {
        int idx = (b - 1) * 1024 + threadIdx.x;
        if (idx >= N_DAGS * 32) return;
        int d = idx >> 5, j = idx & 31;
        const float* row = dag_sum + d * 32;
        float acc = b1[j];
        #pragma unroll
        for (int k = 0; k < 32; k++) acc = fmaf(row[k], W1[(37 + k) * 32 + j], acc);
        g_dagc[idx] = acc;
        return;
    }
    {
        int idx = (b - 626) * 1024 + threadIdx.x;
        if (idx >= N_OBS * 32) return;
        int o = idx >> 5, j = idx & 31;
        const float* row = glob_sum + o * 32;
        float acc = 0.f;
        #pragma unroll
        for (int k = 0; k < 32; k++) acc = fmaf(row[k], W1[(69 + k) * 32 + j], acc);
        g_globc[idx] = acc;
    }
}

__global__ __launch_bounds__(256)
void segid_kernel() {
    int t = blockIdx.x * blockDim.x + threadIdx.x;
    int i0 = t * 4;
    if (i0 >= N_NODES) return;
    int lo = 0, hi = N_DAGS - 1;
    int lo2 = 0, hi2 = N_OBS - 1;
    while (lo < hi || lo2 < hi2) {
        if (lo < hi) {
            int mid = (lo + hi + 1) >> 1;
            if (g_dag_off[mid] <= i0) lo = mid; else hi = mid - 1;
        }
        if (lo2 < hi2) {
            int mid = (lo2 + hi2 + 1) >> 1;
            if (g_obs_off[mid] <= i0) lo2 = mid; else hi2 = mid - 1;
        }
    }
    uint32_t res[4];
    #pragma unroll
    for (int j = 0; j < 4; j++) {
        int i = i0 + j;
        while (lo  < N_DAGS - 1 && g_dag_off[lo + 1]  <= i) lo++;
        while (lo2 < N_OBS - 1  && g_obs_off[lo2 + 1] <= i) lo2++;
        res[j] = (uint32_t)lo | ((uint32_t)lo2 << 16);
    }
    *(uint4*)(g_seg + i0) = make_uint4(res[0], res[1], res[2], res[3]);
}

// =================== main: fragment-chained MLP, incremental pointers ===================
__global__ __launch_bounds__(128, 4)
void main_kernel(const float* __restrict__ x,
                 const float* __restrict__ emb,
                 const void* __restrict__ mask_raw,
                 const float* __restrict__ W1,
                 const float* __restrict__ W2, const float* __restrict__ b2,
                 const float* __restrict__ W3, const float* __restrict__ b3,
                 const float* __restrict__ W4, const float* __restrict__ b4,
                 float* __restrict__ out) {
    __shared__ float wm[4], ws[4];

    int tid = threadIdx.x;
    int wid = tid >> 5, lane = tid & 31;
    int g = lane >> 2, c = lane & 3;

    // ---- W1 fragments (hi/lo) ----
    uint32_t Bh[3][4][2], Bl[3][4][2];
    #pragma unroll
    for (int s = 0; s < 3; s++) {
        #pragma unroll
        for (int n = 0; n < 4; n++) {
            int col = 8 * n + g;
            int kk = 16 * s + 2 * c;
            w1pair(W1, kk,     col, Bh[s][n][0], Bl[s][n][0]);
            w1pair(W1, kk + 8, col, Bh[s][n][1], Bl[s][n][1]);
        }
    }
    // ---- W2 fragments ----
    uint32_t B2h[2][2][2], B2l[2][2][2];
    #pragma unroll
    for (int s = 0; s < 2; s++) {
        #pragma unroll
        for (int nt = 0; nt < 2; nt++) {
            int col = 8 * nt + g;
            int kk = 16 * s + 2 * c;
            float2 v0 = make_float2(__ldg(W2 + kk * 16 + col),       __ldg(W2 + (kk + 1) * 16 + col));
            float2 v1 = make_float2(__ldg(W2 + (kk + 8) * 16 + col), __ldg(W2 + (kk + 9) * 16 + col));
            split2(v0, B2h[s][nt][0], B2l[s][nt][0]);
            split2(v1, B2h[s][nt][1], B2l[s][nt][1]);
        }
    }
    // ---- W3 fragments ----
    uint32_t B3h[2], B3l[2];
    {
        int kk = 2 * c;
        float2 v0 = make_float2(__ldg(W3 + kk * 8 + g),       __ldg(W3 + (kk + 1) * 8 + g));
        float2 v1 = make_float2(__ldg(W3 + (kk + 8) * 8 + g), __ldg(W3 + (kk + 9) * 8 + g));
        split2(v0, B3h[0], B3l[0]);
        split2(v1, B3h[1], B3l[1]);
    }
    float2 b2v0 = *(const float2*)(b2 + 2 * c);
    float2 b2v1 = *(const float2*)(b2 + 8 + 2 * c);
    float2 b3v  = *(const float2*)(b3 + 2 * c);
    float2 w4v  = *(const float2*)(W4 + 2 * c);
    float  vb4  = __ldg(b4);
    int mode = g_mask_mode;
    int msz  = (mode == 0) ? 1 : 4;

    float osm_m = FLT_NEG, osm_s = 0.f;
    int stride = gridDim.x;

    // ---- incremental warp-base pointers (no per-iteration IMAD chains) ----
    int base0 = blockIdx.x * 128 + wid * 32;
    const char* embW  = (const char*)emb + (size_t)base0 * 128;
    const char* xW    = (const char*)x + (size_t)base0 * 20;
    const uint32_t* segW = g_seg + base0;
    const char* maskW = (const char*)mask_raw + (size_t)base0 * msz;
    float* outW = out + base0;
    const size_t embInc  = (size_t)stride * 128 * 128;
    const size_t xInc    = (size_t)stride * 128 * 20;
    const int    segInc  = stride * 128;
    const size_t maskInc = (size_t)stride * 128 * msz;

    for (int tile = blockIdx.x; tile < N_TILES; tile += stride) {
        // ---- L2 prefetch of next tile's working set ----
        if (tile + stride < N_TILES) {
            pf_l2(embW + embInc + (size_t)lane * 128);
            if (lane < 11) pf_l2(xW + xInc + lane * 32);
            if (lane == 11) pf_l2((const char*)(segW + segInc));
            if (lane == 12) pf_l2(maskW + maskInc);
        }

        #pragma unroll
        for (int m = 0; m < 2; m++) {
            int l0 = m * 16 + g;     // local row (0..31)
            int l1i = l0 + 8;

            // hoisted seg + mask loads (local-index addressing)
            uint32_t sid0 = segW[l0], sid1 = segW[l1i];
            bool mv0, mv1;
            if (mode == 0) {
                mv0 = ((const unsigned char*)maskW)[l0] != 0;
                mv1 = ((const unsigned char*)maskW)[l1i] != 0;
            } else if (mode == 1) {
                mv0 = ((const int*)maskW)[l0] != 0;
                mv1 = ((const int*)maskW)[l1i] != 0;
            } else {
                mv0 = ((const float*)maskW)[l0] != 0.f;
                mv1 = ((const float*)maskW)[l1i] != 0.f;
            }

            // ---- layer 1 (36 HMMA) ----
            float accD[4][4];
            #pragma unroll
            for (int n = 0; n < 4; n++)
                #pragma unroll
                for (int q = 0; q < 4; q++) accD[n][q] = 0.f;

            const float2* e0 = (const float2*)(embW + (size_t)l0 * 128);
            const float2* e1 = (const float2*)(embW + (size_t)l1i * 128);
            #pragma unroll
            for (int s = 0; s < 3; s++) {
                float2 p0a, p1a, p0b, p1b;
                if (s < 2) {
                    p0a = e0[c + 8 * s];
                    p1a = e1[c + 8 * s];
                    p0b = e0[c + 8 * s + 4];
                    p1b = e1[c + 8 * s + 4];
                } else {
                    p0a = xpairp(xW + l0 * 20, c);
                    p1a = xpairp(xW + l1i * 20, c);
                    p0b = make_float2(0.f, 0.f);
                    p1b = make_float2(0.f, 0.f);
                }
                uint32_t ah0, al0, ah1, al1, ah2, al2, ah3, al3;
                split2(p0a, ah0, al0);
                split2(p1a, ah1, al1);
                split2(p0b, ah2, al2);
                split2(p1b, ah3, al3);
                #pragma unroll
                for (int n = 0; n < 4; n++) {
                    MMA_BF16(accD[n], ah0, ah1, ah2, ah3, Bh[s][n][0], Bh[s][n][1]);
                    MMA_BF16(accD[n], ah0, ah1, ah2, ah3, Bl[s][n][0], Bl[s][n][1]);
                    MMA_BF16(accD[n], al0, al1, al2, al3, Bh[s][n][0], Bh[s][n][1]);
                }
            }

            // ---- bias + relu in fragment layout ----
            const float* dc0 = g_dagc  + (sid0 & 0xFFFFu) * 32;
            const float* gc0 = g_globc + (sid0 >> 16) * 32;
            const float* dc1 = g_dagc  + (sid1 & 0xFFFFu) * 32;
            const float* gc1 = g_globc + (sid1 >> 16) * 32;
            #pragma unroll
            for (int n = 0; n < 4; n++) {
                int col = 8 * n + 2 * c;
                float2 a0 = *(const float2*)(dc0 + col);
                float2 g0 = *(const float2*)(gc0 + col);
                float2 a1 = *(const float2*)(dc1 + col);
                float2 g1 = *(const float2*)(gc1 + col);
                accD[n][0] = fmaxf(accD[n][0] + a0.x + g0.x, 0.f);
                accD[n][1] = fmaxf(accD[n][1] + a0.y + g0.y, 0.f);
                accD[n][2] = fmaxf(accD[n][2] + a1.x + g1.x, 0.f);
                accD[n][3] = fmaxf(accD[n][3] + a1.y + g1.y, 0.f);
            }

            // ---- layer 2 (12 HMMA) ----
            float accE[2][4];
            #pragma unroll
            for (int nt = 0; nt < 2; nt++)
                #pragma unroll
                for (int q = 0; q < 4; q++) accE[nt][q] = 0.f;
            #pragma unroll
            for (int s = 0; s < 2; s++) {
                uint32_t Ah[4], Al[4];
                split2(make_float2(accD[2 * s][0],     accD[2 * s][1]),     Ah[0], Al[0]);
                split2(make_float2(accD[2 * s][2],     accD[2 * s][3]),     Ah[1], Al[1]);
                split2(make_float2(accD[2 * s + 1][0], accD[2 * s + 1][1]), Ah[2], Al[2]);
                split2(make_float2(accD[2 * s + 1][2], accD[2 * s + 1][3]), Ah[3], Al[3]);
                #pragma unroll
                for (int nt = 0; nt < 2; nt++) {
                    MMA_BF16(accE[nt], Ah[0], Ah[1], Ah[2], Ah[3], B2h[s][nt][0], B2h[s][nt][1]);
                    MMA_BF16(accE[nt], Ah[0], Ah[1], Ah[2], Ah[3], B2l[s][nt][0], B2l[s][nt][1]);
                    MMA_BF16(accE[nt], Al[0], Al[1], Al[2], Al[3], B2h[s][nt][0], B2h[s][nt][1]);
                }
            }
            #pragma unroll
            for (int nt = 0; nt < 2; nt++) {
                float2 bb = nt ? b2v1 : b2v0;
                accE[nt][0] = fmaxf(accE[nt][0] + bb.x, 0.f);
                accE[nt][1] = fmaxf(accE[nt][1] + bb.y, 0.f);
                accE[nt][2] = fmaxf(accE[nt][2] + bb.x, 0.f);
                accE[nt][3] = fmaxf(accE[nt][3] + bb.y, 0.f);
            }

            // ---- layer 3 (3 HMMA) ----
            float accF[4] = {0.f, 0.f, 0.f, 0.f};
            {
                uint32_t Ah[4], Al[4];
                split2(make_float2(accE[0][0], accE[0][1]), Ah[0], Al[0]);
                split2(make_float2(accE[0][2], accE[0][3]), Ah[1], Al[1]);
                split2(make_float2(accE[1][0], accE[1][1]), Ah[2], Al[2]);
                split2(make_float2(accE[1][2], accE[1][3]), Ah[3], Al[3]);
                MMA_BF16(accF, Ah[0], Ah[1], Ah[2], Ah[3], B3h[0], B3h[1]);
                MMA_BF16(accF, Ah[0], Ah[1], Ah[2], Ah[3], B3l[0], B3l[1]);
                MMA_BF16(accF, Al[0], Al[1], Al[2], Al[3], B3h[0], B3h[1]);
            }

            // ---- layer 4 + mask + online softmax ----
            float p0 = fmaxf(accF[0] + b3v.x, 0.f) * w4v.x + fmaxf(accF[1] + b3v.y, 0.f) * w4v.y;
            float p1 = fmaxf(accF[2] + b3v.x, 0.f) * w4v.x + fmaxf(accF[3] + b3v.y, 0.f) * w4v.y;
            p0 += __shfl_xor_sync(0xffffffffu, p0, 1);
            p1 += __shfl_xor_sync(0xffffffffu, p1, 1);
            p0 += __shfl_xor_sync(0xffffffffu, p0, 2);
            p1 += __shfl_xor_sync(0xffffffffu, p1, 2);

            if (c == 0) {
                float sc0 = mv0 ? (p0 + vb4) : FLT_NEG;
                float sc1 = mv1 ? (p1 + vb4) : FLT_NEG;
                outW[l0]  = sc0;
                outW[l1i] = sc1;
                float mn = fmaxf(osm_m, fmaxf(sc0, sc1));
                osm_s = osm_s * __expf(osm_m - mn) + __expf(sc0 - mn) + __expf(sc1 - mn);
                osm_m = mn;
            }
        }

        embW  += embInc;
        xW    += xInc;
        segW  += segInc;
        maskW += maskInc;
        outW  += segInc;
    }

    // ---- reduce (m,s) warp -> CTA ----
    #pragma unroll
    for (int o = 16; o; o >>= 1) {
        float m2 = __shfl_xor_sync(0xffffffffu, osm_m, o);
        float s2 = __shfl_xor_sync(0xffffffffu, osm_s, o);
        osm_combine(osm_m, osm_s, m2, s2);
    }
    if (lane == 0) { wm[wid] = osm_m; ws[wid] = osm_s; }
    __syncthreads();
    if (tid == 0) {
        float m = wm[0], s = ws[0];
        osm_combine(m, s, wm[1], ws[1]);
        osm_combine(m, s, wm[2], ws[2]);
        osm_combine(m, s, wm[3], ws[3]);
        g_cta_m[blockIdx.x] = m;
        g_cta_s[blockIdx.x] = s;
    }
}

// =================== finalize (merge folded in) ===================
__global__ __launch_bounds__(256)
void fin_kernel(float4* __restrict__ out4, int n4, int nctas) {
    __shared__ float sred[64];
    __shared__ float s_mx, s_inv;
    int tid = threadIdx.x;
    {
        float m = FLT_NEG, s = 0.f;
        for (int i = tid; i < nctas; i += 256)
            osm_combine(m, s, g_cta_m[i], g_cta_s[i]);
        #pragma unroll
        for (int o = 16; o; o >>= 1) {
            float m2 = __shfl_xor_sync(0xffffffffu, m, o);
            float s2 = __shfl_xor_sync(0xffffffffu, s, o);
            osm_combine(m, s, m2, s2);
        }
        if ((tid & 31) == 0) { sred[tid >> 5] = m; sred[8 + (tid >> 5)] = s; }
        __syncthreads();
        if (tid == 0) {
            float mm = sred[0], ss = sred[8];
            #pragma unroll
            for (int w = 1; w < 8; w++) osm_combine(mm, ss, sred[w], sred[8 + w]);
            s_mx = mm;
            s_inv = 1.0f / ss;
        }
        __syncthreads();
    }
    float inv = s_inv, mx = s_mx;
    for (int i = blockIdx.x * blockDim.x + tid; i < n4; i += gridDim.x * blockDim.x) {
        float4 v = out4[i];
        v.x = __expf(v.x - mx) * inv;
        v.y = __expf(v.y - mx) * inv;
        v.z = __expf(v.z - mx) * inv;
        v.w = __expf(v.w - mx) * inv;
        out4[i] = v;
    }
}

// =================== launch ===================
extern "C" void kernel_launch(void* const* d_in, const int* in_sizes, int n_in,
                              void* d_out, int out_size) {
    const float* x        = (const float*)d_in[0];
    const float* emb      = (const float*)d_in[1];
    const float* dag_sum  = (const float*)d_in[2];
    const float* glob_sum = (const float*)d_in[3];
    const void*  cnt_dag  = d_in[4];
    const void*  cnt_obs  = d_in[5];
    const void*  mask     = d_in[6];
    const float* W1 = (const float*)d_in[7];
    const float* b1 = (const float*)d_in[8];
    const float* W2 = (const float*)d_in[9];
    const float* b2 = (const float*)d_in[10];
    const float* W3 = (const float*)d_in[11];
    const float* b3 = (const float*)d_in[12];
    const float* W4 = (const float*)d_in[13];
    const float* b4 = (const float*)d_in[14];
    float* out = (float*)d_out;

    static int grid_main = 0;
    static cudaStream_t s1 = nullptr;
    static cudaEvent_t evA = nullptr, evB = nullptr;
    if (grid_main == 0) {
        int nb = 1, nsm = 148;
        cudaOccupancyMaxActiveBlocksPerMultiprocessor(&nb, main_kernel, 128, 0);
        cudaDeviceGetAttribute(&nsm, cudaDevAttrMultiProcessorCount, 0);
        if (nb < 1) nb = 1;
        grid_main = nb * nsm;
        if (grid_main > 1024) grid_main = 1024;
        if (grid_main > N_TILES) grid_main = N_TILES;
        cudaStreamCreateWithFlags(&s1, cudaStreamNonBlocking);
        cudaEventCreateWithFlags(&evA, cudaEventDisableTiming);
        cudaEventCreateWithFlags(&evB, cudaEventDisableTiming);
    }

    // fork: contrib/detect on side stream, scan->segid on main stream
    cudaEventRecord(evA, 0);
    cudaStreamWaitEvent(s1, evA, 0);
    scan_kernel<<<2, 1024>>>(cnt_dag, cnt_obs);                                  // launch 1
    contrib_kernel<<<658, 1024, 0, s1>>>(dag_sum, glob_sum, W1, b1,
                                         (const unsigned char*)mask);            // launch 2
    segid_kernel<<<(N_NODES / 4 + 255) / 256, 256>>>();                          // launch 3
    cudaEventRecord(evB, s1);
    cudaStreamWaitEvent(0, evB, 0);
    main_kernel<<<grid_main, 128>>>(x, emb, mask, W1, W2, b2, W3, b3, W4, b4, out); // launch 4
    fin_kernel<<<1024, 256>>>((float4*)out, N_NODES / 4, grid_main);             // launch 5
}

// round 15
// speedup vs baseline: 1.1824x; 1.1824x over previous
#include <cuda_runtime.h>
#include <cuda_bf16.h>
#include <math.h>
#include <cstdint>

#define N_NODES 2000000
#define N_DAGS  20000
#define N_OBS   1000
#define N_TILES (N_NODES / 128)   // 15625
#define FLT_NEG (-3.402823466e+38f)

// ---------------- device scratch ----------------
__device__ int      g_dag_off[N_DAGS + 1];
__device__ int      g_obs_off[N_OBS + 1];
__device__ __align__(16) float g_dagc[N_DAGS * 32];
__device__ __align__(16) float g_globc[N_OBS * 32];
__device__ __align__(16) uint32_t g_seg[N_NODES];
__device__ float    g_cta_m[1024];
__device__ float    g_cta_s[1024];
__device__ int      g_mask_mode;

// ---------------- helpers ----------------
__device__ __forceinline__ uint32_t bf2(float lo, float hi) {
    uint32_t r;
    asm("cvt.rn.bf16x2.f32 %0, %1, %2;" : "=r"(r) : "f"(hi), "f"(lo));
    return r;
}
__device__ __forceinline__ void split2(float2 v, uint32_t& h, uint32_t& l) {
    h = bf2(v.x, v.y);
    float h0 = __uint_as_float(h << 16);
    float h1 = __uint_as_float(h & 0xFFFF0000u);
    l = bf2(v.x - h0, v.y - h1);
}
__device__ __forceinline__ void pf_l2(const void* p) {
    asm volatile("prefetch.global.L2 [%0];" :: "l"(p));
}

#define MMA_BF16(d, a0, a1, a2, a3, b0, b1) \
    asm volatile("mma.sync.aligned.m16n8k16.row.col.f32.bf16.bf16.f32 " \
        "{%0,%1,%2,%3}, {%4,%5,%6,%7}, {%8,%9}, {%0,%1,%2,%3};" \
        : "+f"((d)[0]), "+f"((d)[1]), "+f"((d)[2]), "+f"((d)[3]) \
        : "r"(a0), "r"(a1), "r"(a2), "r"(a3), "r"(b0), "r"(b1))

__device__ __forceinline__ float wp_elem(const float* W1, int k, int col) {
    if (k < 32) return __ldg(W1 + (5 + k) * 32 + col);
    if (k < 37) return __ldg(W1 + (k - 32) * 32 + col);
    return 0.f;
}
__device__ __forceinline__ void w1pair(const float* W1, int k, int col, uint32_t& h, uint32_t& l) {
    float2 v = make_float2(wp_elem(W1, k, col), wp_elem(W1, k + 1, col));
    split2(v, h, l);
}
__device__ __forceinline__ float2 xpair(const float* x, int node, int c) {
    const float* xr = x + (size_t)node * 5;
    float2 r = make_float2(0.f, 0.f);
    if (c == 0) { r.x = __ldg(xr + 0); r.y = __ldg(xr + 1); }
    else if (c == 1) { r.x = __ldg(xr + 2); r.y = __ldg(xr + 3); }
    else if (c == 2) { r.x = __ldg(xr + 4); }
    return r;
}
__device__ __forceinline__ void osm_combine(float& m, float& s, float m2, float s2) {
    float mn = fmaxf(m, m2);
    s = s * __expf(m - mn) + s2 * __expf(m2 - mn);
    m = mn;
}

// =================== prep bodies ===================
__device__ void scan_body(const void* counts_raw, int n, int total, int* off) {
    __shared__ long long sbuf[1024];
    __shared__ long long carry;
    __shared__ int mode;
    int tid = threadIdx.x;
    const int* c32 = (const int*)counts_raw;
    long long s = 0;
    for (int i = tid; i < n; i += 1024) s += (long long)c32[i];
    sbuf[tid] = s;
    __syncthreads();
    for (int st = 512; st; st >>= 1) {
        if (tid < st) sbuf[tid] += sbuf[tid + st];
        __syncthreads();
    }
    if (tid == 0) { mode = (sbuf[0] == (long long)total) ? 0 : 1; carry = 0; }
    __syncthreads();
    const long long* c64 = (const long long*)counts_raw;
    for (int base = 0; base < n; base += 1024) {
        int i = base + tid;
        long long v = 0;
        if (i < n) v = (mode == 0) ? (long long)c32[i] : c64[i];
        sbuf[tid] = v;
        __syncthreads();
        for (int st = 1; st < 1024; st <<= 1) {
            long long t = (tid >= st) ? sbuf[tid - st] : 0;
            __syncthreads();
            sbuf[tid] += t;
            __syncthreads();
        }
        long long incl = sbuf[tid];
        if (i < n) off[i] = (int)(carry + incl - v);
        __syncthreads();
        if (tid == 0) carry += sbuf[1023];
        __syncthreads();
    }
    if (tid == 0) off[n] = (int)carry;
}

__device__ void detect_body(const unsigned char* m) {
    __shared__ int c1, c2;
    if (threadIdx.x == 0) { c1 = 0; c2 = 0; }
    __syncthreads();
    int l1 = 0, l2 = 0;
    for (int i = threadIdx.x; i < 4096; i += blockDim.x) {
        unsigned char b = m[i];
        if (b) { int r = i & 3; if (r == 1) l1++; if (r == 2) l2++; }
    }
    atomicAdd(&c1, l1); atomicAdd(&c2, l2);
    __syncthreads();
    if (threadIdx.x == 0) {
        if (c1 == 0 && c2 == 0)      g_mask_mode = 1;
        else if (c1 == 0 && c2 > 0)  g_mask_mode = 2;
        else                         g_mask_mode = 0;
    }
}

__global__ void prep_kernel(const void* __restrict__ cnt_dag, const void* __restrict__ cnt_obs,
                            const float* __restrict__ dag_sum, const float* __restrict__ glob_sum,
                            const float* __restrict__ W1, const float* __restrict__ b1,
                            const unsigned char* __restrict__ mask) {
    int b = blockIdx.x;
    if (b == 0) { scan_body(cnt_dag, N_DAGS, N_NODES, g_dag_off); return; }
    if (b == 1) { scan_body(cnt_obs, N_OBS, N_NODES, g_obs_off); return; }
    if (b == 2) { detect_body(mask); return; }
    if (b < 628) {
        int idx = (b - 3) * 1024 + threadIdx.x;
        if (idx >= N_DAGS * 32) return;
        int d = idx >> 5, j = idx & 31;
        const float* row = dag_sum + d * 32;
        float acc = b1[j];
        #pragma unroll
        for (int k = 0; k < 32; k++) acc = fmaf(row[k], W1[(37 + k) * 32 + j], acc);
        g_dagc[idx] = acc;
        return;
    }
    {
        int idx = (b - 628) * 1024 + threadIdx.x;
        if (idx >= N_OBS * 32) return;
        int o = idx >> 5, j = idx & 31;
        const float* row = glob_sum + o * 32;
        float acc = 0.f;
        #pragma unroll
        for (int k = 0; k < 32; k++) acc = fmaf(row[k], W1[(69 + k) * 32 + j], acc);
        g_globc[idx] = acc;
    }
}

__global__ __launch_bounds__(256)
void segid_kernel() {
    int t = blockIdx.x * blockDim.x + threadIdx.x;
    int i0 = t * 4;
    if (i0 >= N_NODES) return;
    int lo = 0, hi = N_DAGS - 1;
    int lo2 = 0, hi2 = N_OBS - 1;
    while (lo < hi || lo2 < hi2) {
        if (lo < hi) {
            int mid = (lo + hi + 1) >> 1;
            if (g_dag_off[mid] <= i0) lo = mid; else hi = mid - 1;
        }
        if (lo2 < hi2) {
            int mid = (lo2 + hi2 + 1) >> 1;
            if (g_obs_off[mid] <= i0) lo2 = mid; else hi2 = mid - 1;
        }
    }
    uint32_t res[4];
    #pragma unroll
    for (int j = 0; j < 4; j++) {
        int i = i0 + j;
        while (lo  < N_DAGS - 1 && g_dag_off[lo + 1]  <= i) lo++;
        while (lo2 < N_OBS - 1  && g_obs_off[lo2 + 1] <= i) lo2++;
        res[j] = (uint32_t)lo | ((uint32_t)lo2 << 16);
    }
    *(uint4*)(g_seg + i0) = make_uint4(res[0], res[1], res[2], res[3]);
}

// =================== main: fragment-chained MLP, 4 CTAs/SM (R10 config) ===================
__global__ __launch_bounds__(128, 4)
void main_kernel(const float* __restrict__ x,
                 const float* __restrict__ emb,
                 const void* __restrict__ mask_raw,
                 const float* __restrict__ W1,
                 const float* __restrict__ W2, const float* __restrict__ b2,
                 const float* __restrict__ W3, const float* __restrict__ b3,
                 const float* __restrict__ W4, const float* __restrict__ b4,
                 float* __restrict__ out) {
    __shared__ float wm[4], ws[4];

    int tid = threadIdx.x;
    int wid = tid >> 5, lane = tid & 31;
    int g = lane >> 2, c = lane & 3;

    // ---- W1 fragments (hi/lo) ----
    uint32_t Bh[3][4][2], Bl[3][4][2];
    #pragma unroll
    for (int s = 0; s < 3; s++) {
        #pragma unroll
        for (int n = 0; n < 4; n++) {
            int col = 8 * n + g;
            int kk = 16 * s + 2 * c;
            w1pair(W1, kk,     col, Bh[s][n][0], Bl[s][n][0]);
            w1pair(W1, kk + 8, col, Bh[s][n][1], Bl[s][n][1]);
        }
    }
    // ---- W2 fragments ----
    uint32_t B2h[2][2][2], B2l[2][2][2];
    #pragma unroll
    for (int s = 0; s < 2; s++) {
        #pragma unroll
        for (int nt = 0; nt < 2; nt++) {
            int col = 8 * nt + g;
            int kk = 16 * s + 2 * c;
            float2 v0 = make_float2(__ldg(W2 + kk * 16 + col),       __ldg(W2 + (kk + 1) * 16 + col));
            float2 v1 = make_float2(__ldg(W2 + (kk + 8) * 16 + col), __ldg(W2 + (kk + 9) * 16 + col));
            split2(v0, B2h[s][nt][0], B2l[s][nt][0]);
            split2(v1, B2h[s][nt][1], B2l[s][nt][1]);
        }
    }
    // ---- W3 fragments ----
    uint32_t B3h[2], B3l[2];
    {
        int kk = 2 * c;
        float2 v0 = make_float2(__ldg(W3 + kk * 8 + g),       __ldg(W3 + (kk + 1) * 8 + g));
        float2 v1 = make_float2(__ldg(W3 + (kk + 8) * 8 + g), __ldg(W3 + (kk + 9) * 8 + g));
        split2(v0, B3h[0], B3l[0]);
        split2(v1, B3h[1], B3l[1]);
    }
    float2 b2v0 = *(const float2*)(b2 + 2 * c);
    float2 b2v1 = *(const float2*)(b2 + 8 + 2 * c);
    float2 b3v  = *(const float2*)(b3 + 2 * c);
    float2 w4v  = *(const float2*)(W4 + 2 * c);
    float  vb4  = __ldg(b4);
    int mode = g_mask_mode;

    float osm_m = FLT_NEG, osm_s = 0.f;
    int stride = gridDim.x;

    for (int tile = blockIdx.x; tile < N_TILES; tile += stride) {
        int base = tile * 128 + wid * 32;

        // ---- prefetch next tile's working set into L2 ----
        {
            int ntile = tile + stride;
            if (ntile < N_TILES) {
                int nbase = ntile * 128 + wid * 32;
                pf_l2(emb + (size_t)(nbase + lane) * 32);
                if (lane < 11) pf_l2(x + (size_t)nbase * 5 + lane * 32);
                if (lane == 11) pf_l2(g_seg + nbase);
                if (lane == 12) pf_l2((const char*)mask_raw + (size_t)nbase * (mode == 0 ? 1 : 4));
            }
        }

        #pragma unroll
        for (int m = 0; m < 2; m++) {
            int r0 = base + m * 16 + g;
            int r1 = r0 + 8;

            // hoisted seg + mask loads
            uint32_t sid0 = g_seg[r0], sid1 = g_seg[r1];
            bool mv0, mv1;
            if (mode == 0) {
                mv0 = ((const unsigned char*)mask_raw)[r0] != 0;
                mv1 = ((const unsigned char*)mask_raw)[r1] != 0;
            } else if (mode == 1) {
                mv0 = ((const int*)mask_raw)[r0] != 0;
                mv1 = ((const int*)mask_raw)[r1] != 0;
            } else {
                mv0 = ((const float*)mask_raw)[r0] != 0.f;
                mv1 = ((const float*)mask_raw)[r1] != 0.f;
            }

            // ---- layer 1 (36 HMMA) ----
            float accD[4][4];
            #pragma unroll
            for (int n = 0; n < 4; n++)
                #pragma unroll
                for (int q = 0; q < 4; q++) accD[n][q] = 0.f;

            const float2* e0 = (const float2*)(emb + (size_t)r0 * 32);
            const float2* e1 = (const float2*)(emb + (size_t)r1 * 32);
            #pragma unroll
            for (int s = 0; s < 3; s++) {
                float2 p0a, p1a, p0b, p1b;
                if (s < 2) {
                    p0a = e0[c + 8 * s];
                    p1a = e1[c + 8 * s];
                    p0b = e0[c + 8 * s + 4];
                    p1b = e1[c + 8 * s + 4];
                } else {
                    p0a = xpair(x, r0, c);
                    p1a = xpair(x, r1, c);
                    p0b = make_float2(0.f, 0.f);
                    p1b = make_float2(0.f, 0.f);
                }
                uint32_t ah0, al0, ah1, al1, ah2, al2, ah3, al3;
                split2(p0a, ah0, al0);
                split2(p1a, ah1, al1);
                split2(p0b, ah2, al2);
                split2(p1b, ah3, al3);
                #pragma unroll
                for (int n = 0; n < 4; n++) {
                    MMA_BF16(accD[n], ah0, ah1, ah2, ah3, Bh[s][n][0], Bh[s][n][1]);
                    MMA_BF16(accD[n], ah0, ah1, ah2, ah3, Bl[s][n][0], Bl[s][n][1]);
                    MMA_BF16(accD[n], al0, al1, al2, al3, Bh[s][n][0], Bh[s][n][1]);
                }
            }

            // ---- bias + relu in fragment layout ----
            const float* dc0 = g_dagc  + (sid0 & 0xFFFFu) * 32;
            const float* gc0 = g_globc + (sid0 >> 16) * 32;
            const float* dc1 = g_dagc  + (sid1 & 0xFFFFu) * 32;
            const float* gc1 = g_globc + (sid1 >> 16) * 32;
            #pragma unroll
            for (int n = 0; n < 4; n++) {
                int col = 8 * n + 2 * c;
                float2 a0 = *(const float2*)(dc0 + col);
                float2 g0 = *(const float2*)(gc0 + col);
                float2 a1 = *(const float2*)(dc1 + col);
                float2 g1 = *(const float2*)(gc1 + col);
                accD[n][0] = fmaxf(accD[n][0] + a0.x + g0.x, 0.f);
                accD[n][1] = fmaxf(accD[n][1] + a0.y + g0.y, 0.f);
                accD[n][2] = fmaxf(accD[n][2] + a1.x + g1.x, 0.f);
                accD[n][3] = fmaxf(accD[n][3] + a1.y + g1.y, 0.f);
            }

            // ---- layer 2 (12 HMMA) ----
            float accE[2][4];
            #pragma unroll
            for (int nt = 0; nt < 2; nt++)
                #pragma unroll
                for (int q = 0; q < 4; q++) accE[nt][q] = 0.f;
            #pragma unroll
            for (int s = 0; s < 2; s++) {
                uint32_t Ah[4], Al[4];
                split2(make_float2(accD[2 * s][0],     accD[2 * s][1]),     Ah[0], Al[0]);
                split2(make_float2(accD[2 * s][2],     accD[2 * s][3]),     Ah[1], Al[1]);
                split2(make_float2(accD[2 * s + 1][0], accD[2 * s + 1][1]), Ah[2], Al[2]);
                split2(make_float2(accD[2 * s + 1][2], accD[2 * s + 1][3]), Ah[3], Al[3]);
                #pragma unroll
                for (int nt = 0; nt < 2; nt++) {
                    MMA_BF16(accE[nt], Ah[0], Ah[1], Ah[2], Ah[3], B2h[s][nt][0], B2h[s][nt][1]);
                    MMA_BF16(accE[nt], Ah[0], Ah[1], Ah[2], Ah[3], B2l[s][nt][0], B2l[s][nt][1]);
                    MMA_BF16(accE[nt], Al[0], Al[1], Al[2], Al[3], B2h[s][nt][0], B2h[s][nt][1]);
                }
            }
            #pragma unroll
            for (int nt = 0; nt < 2; nt++) {
                float2 bb = nt ? b2v1 : b2v0;
                accE[nt][0] = fmaxf(accE[nt][0] + bb.x, 0.f);
                accE[nt][1] = fmaxf(accE[nt][1] + bb.y, 0.f);
                accE[nt][2] = fmaxf(accE[nt][2] + bb.x, 0.f);
                accE[nt][3] = fmaxf(accE[nt][3] + bb.y, 0.f);
            }

            // ---- layer 3 (3 HMMA) ----
            float accF[4] = {0.f, 0.f, 0.f, 0.f};
            {
                uint32_t Ah[4], Al[4];
                split2(make_float2(accE[0][0], accE[0][1]), Ah[0], Al[0]);
                split2(make_float2(accE[0][2], accE[0][3]), Ah[1], Al[1]);
                split2(make_float2(accE[1][0], accE[1][1]), Ah[2], Al[2]);
                split2(make_float2(accE[1][2], accE[1][3]), Ah[3], Al[3]);
                MMA_BF16(accF, Ah[0], Ah[1], Ah[2], Ah[3], B3h[0], B3h[1]);
                MMA_BF16(accF, Ah[0], Ah[1], Ah[2], Ah[3], B3l[0], B3l[1]);
                MMA_BF16(accF, Al[0], Al[1], Al[2], Al[3], B3h[0], B3h[1]);
            }

            // ---- layer 4 + mask + online softmax ----
            float p0 = fmaxf(accF[0] + b3v.x, 0.f) * w4v.x + fmaxf(accF[1] + b3v.y, 0.f) * w4v.y;
            float p1 = fmaxf(accF[2] + b3v.x, 0.f) * w4v.x + fmaxf(accF[3] + b3v.y, 0.f) * w4v.y;
            p0 += __shfl_xor_sync(0xffffffffu, p0, 1);
            p1 += __shfl_xor_sync(0xffffffffu, p1, 1);
            p0 += __shfl_xor_sync(0xffffffffu, p0, 2);
            p1 += __shfl_xor_sync(0xffffffffu, p1, 2);

            if (c == 0) {
                float sc0 = mv0 ? (p0 + vb4) : FLT_NEG;
                float sc1 = mv1 ? (p1 + vb4) : FLT_NEG;
                out[r0] = sc0;
                out[r1] = sc1;
                float mn = fmaxf(osm_m, fmaxf(sc0, sc1));
                osm_s = osm_s * __expf(osm_m - mn) + __expf(sc0 - mn) + __expf(sc1 - mn);
                osm_m = mn;
            }
        }
    }

    // ---- reduce (m,s) warp -> CTA ----
    #pragma unroll
    for (int o = 16; o; o >>= 1) {
        float m2 = __shfl_xor_sync(0xffffffffu, osm_m, o);
        float s2 = __shfl_xor_sync(0xffffffffu, osm_s, o);
        osm_combine(osm_m, osm_s, m2, s2);
    }
    if (lane == 0) { wm[wid] = osm_m; ws[wid] = osm_s; }
    __syncthreads();
    if (tid == 0) {
        float m = wm[0], s = ws[0];
        osm_combine(m, s, wm[1], ws[1]);
        osm_combine(m, s, wm[2], ws[2]);
        osm_combine(m, s, wm[3], ws[3]);
        g_cta_m[blockIdx.x] = m;
        g_cta_s[blockIdx.x] = s;
    }
}

// =================== finalize (merge folded in) ===================
__global__ __launch_bounds__(256)
void fin_kernel(float4* __restrict__ out4, int n4, int nctas) {
    __shared__ float sred[64];
    __shared__ float s_mx, s_inv;
    int tid = threadIdx.x;
    {
        float m = FLT_NEG, s = 0.f;
        for (int i = tid; i < nctas; i += 256)
            osm_combine(m, s, g_cta_m[i], g_cta_s[i]);
        #pragma unroll
        for (int o = 16; o; o >>= 1) {
            float m2 = __shfl_xor_sync(0xffffffffu, m, o);
            float s2 = __shfl_xor_sync(0xffffffffu, s, o);
            osm_combine(m, s, m2, s2);
        }
        if ((tid & 31) == 0) { sred[tid >> 5] = m; sred[8 + (tid >> 5)] = s; }
        __syncthreads();
        if (tid == 0) {
            float mm = sred[0], ss = sred[8];
            #pragma unroll
            for (int w = 1; w < 8; w++) osm_combine(mm, ss, sred[w], sred[8 + w]);
            s_mx = mm;
            s_inv = 1.0f / ss;
        }
        __syncthreads();
    }
    float inv = s_inv, mx = s_mx;
    for (int i = blockIdx.x * blockDim.x + tid; i < n4; i += gridDim.x * blockDim.x) {
        float4 v = out4[i];
        v.x = __expf(v.x - mx) * inv;
        v.y = __expf(v.y - mx) * inv;
        v.z = __expf(v.z - mx) * inv;
        v.w = __expf(v.w - mx) * inv;
        out4[i] = v;
    }
}

// =================== launch ===================
extern "C" void kernel_launch(void* const* d_in, const int* in_sizes, int n_in,
                              void* d_out, int out_size) {
    const float* x        = (const float*)d_in[0];
    const float* emb      = (const float*)d_in[1];
    const float* dag_sum  = (const float*)d_in[2];
    const float* glob_sum = (const float*)d_in[3];
    const void*  cnt_dag  = d_in[4];
    const void*  cnt_obs  = d_in[5];
    const void*  mask     = d_in[6];
    const float* W1 = (const float*)d_in[7];
    const float* b1 = (const float*)d_in[8];
    const float* W2 = (const float*)d_in[9];
    const float* b2 = (const float*)d_in[10];
    const float* W3 = (const float*)d_in[11];
    const float* b3 = (const float*)d_in[12];
    const float* W4 = (const float*)d_in[13];
    const float* b4 = (const float*)d_in[14];
    float* out = (float*)d_out;

    static int grid_main = 0;
    if (grid_main == 0) {
        int nb = 1, nsm = 148;
        cudaOccupancyMaxActiveBlocksPerMultiprocessor(&nb, main_kernel, 128, 0);
        cudaDeviceGetAttribute(&nsm, cudaDevAttrMultiProcessorCount, 0);
        if (nb < 1) nb = 1;
        grid_main = nb * nsm;
        if (grid_main > 1024) grid_main = 1024;
        if (grid_main > N_TILES) grid_main = N_TILES;
    }

    prep_kernel<<<660, 1024>>>(cnt_dag, cnt_obs, dag_sum, glob_sum, W1, b1,
                               (const unsigned char*)mask);
    segid_kernel<<<(N_NODES / 4 + 255) / 256, 256>>>();
    main_kernel<<<grid_main, 128>>>(x, emb, mask, W1, W2, b2, W3, b3, W4, b4, out);
    fin_kernel<<<1024, 256>>>((float4*)out, N_NODES / 4, grid_main);
}

// round 16
// speedup vs baseline: 1.2014x; 1.0161x over previous
#include <cuda_runtime.h>
#include <cuda_bf16.h>
#include <math.h>
#include <cstdint>

#define N_NODES 2000000
#define N_DAGS  20000
#define N_OBS   1000
#define N_TILES (N_NODES / 128)   // 15625
#define FLT_NEG (-3.402823466e+38f)

// ---------------- device scratch ----------------
__device__ int      g_dag_off[N_DAGS + 1];
__device__ int      g_obs_off[N_OBS + 1];
__device__ __align__(16) float g_dagc[N_DAGS * 32];
__device__ __align__(16) float g_globc[N_OBS * 32];
__device__ __align__(16) uint32_t g_seg[N_NODES];
__device__ float    g_cta_m[1024];
__device__ float    g_cta_s[1024];
__device__ int      g_mask_mode;

// ---------------- helpers ----------------
__device__ __forceinline__ uint32_t bf2(float lo, float hi) {
    uint32_t r;
    asm("cvt.rn.bf16x2.f32 %0, %1, %2;" : "=r"(r) : "f"(hi), "f"(lo));
    return r;
}
__device__ __forceinline__ void split2(float2 v, uint32_t& h, uint32_t& l) {
    h = bf2(v.x, v.y);
    float h0 = __uint_as_float(h << 16);
    float h1 = __uint_as_float(h & 0xFFFF0000u);
    l = bf2(v.x - h0, v.y - h1);
}
__device__ __forceinline__ void pf_l2(const void* p) {
    asm volatile("prefetch.global.L2 [%0];" :: "l"(p));
}

#define MMA_BF16(d, a0, a1, a2, a3, b0, b1) \
    asm volatile("mma.sync.aligned.m16n8k16.row.col.f32.bf16.bf16.f32 " \
        "{%0,%1,%2,%3}, {%4,%5,%6,%7}, {%8,%9}, {%0,%1,%2,%3};" \
        : "+f"((d)[0]), "+f"((d)[1]), "+f"((d)[2]), "+f"((d)[3]) \
        : "r"(a0), "r"(a1), "r"(a2), "r"(a3), "r"(b0), "r"(b1))

// logical feature k: 0..31 = emb index k, 32..36 = x feature k-32, else 0
__device__ __forceinline__ float wp_elem(const float* W1, int k, int col) {
    if (k < 32) return __ldg(W1 + (5 + k) * 32 + col);
    if (k < 37) return __ldg(W1 + (k - 32) * 32 + col);
    return 0.f;
}
__device__ __forceinline__ void w1pair(const float* W1, int k, int col, uint32_t& h, uint32_t& l) {
    float2 v = make_float2(wp_elem(W1, k, col), wp_elem(W1, k + 1, col));
    split2(v, h, l);
}
__device__ __forceinline__ float2 xpair(const float* x, int node, int c) {
    const float* xr = x + (size_t)node * 5;
    float2 r = make_float2(0.f, 0.f);
    if (c == 0) { r.x = __ldg(xr + 0); r.y = __ldg(xr + 1); }
    else if (c == 1) { r.x = __ldg(xr + 2); r.y = __ldg(xr + 3); }
    else if (c == 2) { r.x = __ldg(xr + 4); }
    return r;
}
__device__ __forceinline__ void osm_combine(float& m, float& s, float m2, float s2) {
    float mn = fmaxf(m, m2);
    s = s * __expf(m - mn) + s2 * __expf(m2 - mn);
    m = mn;
}

// =================== prep bodies ===================
__device__ void scan_body(const void* counts_raw, int n, int total, int* off) {
    __shared__ long long sbuf[1024];
    __shared__ long long carry;
    __shared__ int mode;
    int tid = threadIdx.x;
    const int* c32 = (const int*)counts_raw;
    long long s = 0;
    for (int i = tid; i < n; i += 1024) s += (long long)c32[i];
    sbuf[tid] = s;
    __syncthreads();
    for (int st = 512; st; st >>= 1) {
        if (tid < st) sbuf[tid] += sbuf[tid + st];
        __syncthreads();
    }
    if (tid == 0) { mode = (sbuf[0] == (long long)total) ? 0 : 1; carry = 0; }
    __syncthreads();
    const long long* c64 = (const long long*)counts_raw;
    for (int base = 0; base < n; base += 1024) {
        int i = base + tid;
        long long v = 0;
        if (i < n) v = (mode == 0) ? (long long)c32[i] : c64[i];
        sbuf[tid] = v;
        __syncthreads();
        for (int st = 1; st < 1024; st <<= 1) {
            long long t = (tid >= st) ? sbuf[tid - st] : 0;
            __syncthreads();
            sbuf[tid] += t;
            __syncthreads();
        }
        long long incl = sbuf[tid];
        if (i < n) off[i] = (int)(carry + incl - v);
        __syncthreads();
        if (tid == 0) carry += sbuf[1023];
        __syncthreads();
    }
    if (tid == 0) off[n] = (int)carry;
}

__device__ void detect_body(const unsigned char* m) {
    __shared__ int c1, c2;
    if (threadIdx.x == 0) { c1 = 0; c2 = 0; }
    __syncthreads();
    int l1 = 0, l2 = 0;
    for (int i = threadIdx.x; i < 4096; i += blockDim.x) {
        unsigned char b = m[i];
        if (b) { int r = i & 3; if (r == 1) l1++; if (r == 2) l2++; }
    }
    atomicAdd(&c1, l1); atomicAdd(&c2, l2);
    __syncthreads();
    if (threadIdx.x == 0) {
        if (c1 == 0 && c2 == 0)      g_mask_mode = 1;
        else if (c1 == 0 && c2 > 0)  g_mask_mode = 2;
        else                         g_mask_mode = 0;
    }
}

__global__ void prep_kernel(const void* __restrict__ cnt_dag, const void* __restrict__ cnt_obs,
                            const float* __restrict__ dag_sum, const float* __restrict__ glob_sum,
                            const float* __restrict__ W1, const float* __restrict__ b1,
                            const unsigned char* __restrict__ mask) {
    int b = blockIdx.x;
    if (b == 0) { scan_body(cnt_dag, N_DAGS, N_NODES, g_dag_off); return; }
    if (b == 1) { scan_body(cnt_obs, N_OBS, N_NODES, g_obs_off); return; }
    if (b == 2) { detect_body(mask); return; }
    if (b < 628) {
        int idx = (b - 3) * 1024 + threadIdx.x;
        if (idx >= N_DAGS * 32) return;
        int d = idx >> 5, j = idx & 31;
        const float* row = dag_sum + d * 32;
        float acc = b1[j];
        #pragma unroll
        for (int k = 0; k < 32; k++) acc = fmaf(row[k], W1[(37 + k) * 32 + j], acc);
        g_dagc[idx] = acc;
        return;
    }
    {
        int idx = (b - 628) * 1024 + threadIdx.x;
        if (idx >= N_OBS * 32) return;
        int o = idx >> 5, j = idx & 31;
        const float* row = glob_sum + o * 32;
        float acc = 0.f;
        #pragma unroll
        for (int k = 0; k < 32; k++) acc = fmaf(row[k], W1[(69 + k) * 32 + j], acc);
        g_globc[idx] = acc;
    }
}

__global__ __launch_bounds__(256)
void segid_kernel() {
    int t = blockIdx.x * blockDim.x + threadIdx.x;
    int i0 = t * 4;
    if (i0 >= N_NODES) return;
    int lo = 0, hi = N_DAGS - 1;
    int lo2 = 0, hi2 = N_OBS - 1;
    while (lo < hi || lo2 < hi2) {
        if (lo < hi) {
            int mid = (lo + hi + 1) >> 1;
            if (g_dag_off[mid] <= i0) lo = mid; else hi = mid - 1;
        }
        if (lo2 < hi2) {
            int mid = (lo2 + hi2 + 1) >> 1;
            if (g_obs_off[mid] <= i0) lo2 = mid; else hi2 = mid - 1;
        }
    }
    uint32_t res[4];
    #pragma unroll
    for (int j = 0; j < 4; j++) {
        int i = i0 + j;
        while (lo  < N_DAGS - 1 && g_dag_off[lo + 1]  <= i) lo++;
        while (lo2 < N_OBS - 1  && g_obs_off[lo2 + 1] <= i) lo2++;
        res[j] = (uint32_t)lo | ((uint32_t)lo2 << 16);
    }
    *(uint4*)(g_seg + i0) = make_uint4(res[0], res[1], res[2], res[3]);
}

// =================== main: fragment-chained MLP, float4 emb loads ===================
// K-permutation for s<2: thread (g,c)'s fragment elements map to memory floats
// [16s+4c .. 16s+4c+3] (one float4). B fragments are built with matching rows.
__global__ __launch_bounds__(128, 4)
void main_kernel(const float* __restrict__ x,
                 const float* __restrict__ emb,
                 const void* __restrict__ mask_raw,
                 const float* __restrict__ W1,
                 const float* __restrict__ W2, const float* __restrict__ b2,
                 const float* __restrict__ W3, const float* __restrict__ b3,
                 const float* __restrict__ W4, const float* __restrict__ b4,
                 float* __restrict__ out) {
    __shared__ float wm[4], ws[4];

    int tid = threadIdx.x;
    int wid = tid >> 5, lane = tid & 31;
    int g = lane >> 2, c = lane & 3;

    // ---- W1 fragments (hi/lo), permuted for float4 A loads ----
    uint32_t Bh[3][4][2], Bl[3][4][2];
    #pragma unroll
    for (int s = 0; s < 3; s++) {
        #pragma unroll
        for (int n = 0; n < 4; n++) {
            int col = 8 * n + g;
            if (s < 2) {
                int kk = 16 * s + 4 * c;             // memory-contiguous emb quad
                w1pair(W1, kk,     col, Bh[s][n][0], Bl[s][n][0]);
                w1pair(W1, kk + 2, col, Bh[s][n][1], Bl[s][n][1]);
            } else {
                int kk = 32 + 2 * c;                 // x features (unchanged)
                w1pair(W1, kk,     col, Bh[s][n][0], Bl[s][n][0]);
                w1pair(W1, kk + 8, col, Bh[s][n][1], Bl[s][n][1]);
            }
        }
    }
    // ---- W2 fragments ----
    uint32_t B2h[2][2][2], B2l[2][2][2];
    #pragma unroll
    for (int s = 0; s < 2; s++) {
        #pragma unroll
        for (int nt = 0; nt < 2; nt++) {
            int col = 8 * nt + g;
            int kk = 16 * s + 2 * c;
            float2 v0 = make_float2(__ldg(W2 + kk * 16 + col),       __ldg(W2 + (kk + 1) * 16 + col));
            float2 v1 = make_float2(__ldg(W2 + (kk + 8) * 16 + col), __ldg(W2 + (kk + 9) * 16 + col));
            split2(v0, B2h[s][nt][0], B2l[s][nt][0]);
            split2(v1, B2h[s][nt][1], B2l[s][nt][1]);
        }
    }
    // ---- W3 fragments ----
    uint32_t B3h[2], B3l[2];
    {
        int kk = 2 * c;
        float2 v0 = make_float2(__ldg(W3 + kk * 8 + g),       __ldg(W3 + (kk + 1) * 8 + g));
        float2 v1 = make_float2(__ldg(W3 + (kk + 8) * 8 + g), __ldg(W3 + (kk + 9) * 8 + g));
        split2(v0, B3h[0], B3l[0]);
        split2(v1, B3h[1], B3l[1]);
    }
    float2 b2v0 = *(const float2*)(b2 + 2 * c);
    float2 b2v1 = *(const float2*)(b2 + 8 + 2 * c);
    float2 b3v  = *(const float2*)(b3 + 2 * c);
    float2 w4v  = *(const float2*)(W4 + 2 * c);
    float  vb4  = __ldg(b4);
    int mode = g_mask_mode;

    float osm_m = FLT_NEG, osm_s = 0.f;
    int stride = gridDim.x;

    for (int tile = blockIdx.x; tile < N_TILES; tile += stride) {
        int base = tile * 128 + wid * 32;

        // ---- prefetch next tile's working set into L2 ----
        {
            int ntile = tile + stride;
            if (ntile < N_TILES) {
                int nbase = ntile * 128 + wid * 32;
                pf_l2(emb + (size_t)(nbase + lane) * 32);
                if (lane < 11) pf_l2(x + (size_t)nbase * 5 + lane * 32);
                if (lane == 11) pf_l2(g_seg + nbase);
                if (lane == 12) pf_l2((const char*)mask_raw + (size_t)nbase * (mode == 0 ? 1 : 4));
            }
        }

        #pragma unroll
        for (int m = 0; m < 2; m++) {
            int r0 = base + m * 16 + g;
            int r1 = r0 + 8;

            // hoisted seg + mask loads
            uint32_t sid0 = g_seg[r0], sid1 = g_seg[r1];
            bool mv0, mv1;
            if (mode == 0) {
                mv0 = ((const unsigned char*)mask_raw)[r0] != 0;
                mv1 = ((const unsigned char*)mask_raw)[r1] != 0;
            } else if (mode == 1) {
                mv0 = ((const int*)mask_raw)[r0] != 0;
                mv1 = ((const int*)mask_raw)[r1] != 0;
            } else {
                mv0 = ((const float*)mask_raw)[r0] != 0.f;
                mv1 = ((const float*)mask_raw)[r1] != 0.f;
            }

            // ---- layer 1 (36 HMMA), float4 emb loads ----
            float accD[4][4];
            #pragma unroll
            for (int n = 0; n < 4; n++)
                #pragma unroll
                for (int q = 0; q < 4; q++) accD[n][q] = 0.f;

            const float4* e0q = (const float4*)(emb + (size_t)r0 * 32);
            const float4* e1q = (const float4*)(emb + (size_t)r1 * 32);
            #pragma unroll
            for (int s = 0; s < 3; s++) {
                float2 p0a, p1a, p0b, p1b;
                if (s < 2) {
                    float4 q0 = e0q[4 * s + c];   // one LDG.128 per row
                    float4 q1 = e1q[4 * s + c];
                    p0a = make_float2(q0.x, q0.y);
                    p0b = make_float2(q0.z, q0.w);
                    p1a = make_float2(q1.x, q1.y);
                    p1b = make_float2(q1.z, q1.w);
                } else {
                    p0a = xpair(x, r0, c);
                    p1a = xpair(x, r1, c);
                    p0b = make_float2(0.f, 0.f);
                    p1b = make_float2(0.f, 0.f);
                }
                uint32_t ah0, al0, ah1, al1, ah2, al2, ah3, al3;
                split2(p0a, ah0, al0);
                split2(p1a, ah1, al1);
                split2(p0b, ah2, al2);
                split2(p1b, ah3, al3);
                #pragma unroll
                for (int n = 0; n < 4; n++) {
                    MMA_BF16(accD[n], ah0, ah1, ah2, ah3, Bh[s][n][0], Bh[s][n][1]);
                    MMA_BF16(accD[n], ah0, ah1, ah2, ah3, Bl[s][n][0], Bl[s][n][1]);
                    MMA_BF16(accD[n], al0, al1, al2, al3, Bh[s][n][0], Bh[s][n][1]);
                }
            }

            // ---- bias + relu in fragment layout ----
            const float* dc0 = g_dagc  + (sid0 & 0xFFFFu) * 32;
            const float* gc0 = g_globc + (sid0 >> 16) * 32;
            const float* dc1 = g_dagc  + (sid1 & 0xFFFFu) * 32;
            const float* gc1 = g_globc + (sid1 >> 16) * 32;
            #pragma unroll
            for (int n = 0; n < 4; n++) {
                int col = 8 * n + 2 * c;
                float2 a0 = *(const float2*)(dc0 + col);
                float2 g0 = *(const float2*)(gc0 + col);
                float2 a1 = *(const float2*)(dc1 + col);
                float2 g1 = *(const float2*)(gc1 + col);
                accD[n][0] = fmaxf(accD[n][0] + a0.x + g0.x, 0.f);
                accD[n][1] = fmaxf(accD[n][1] + a0.y + g0.y, 0.f);
                accD[n][2] = fmaxf(accD[n][2] + a1.x + g1.x, 0.f);
                accD[n][3] = fmaxf(accD[n][3] + a1.y + g1.y, 0.f);
            }

            // ---- layer 2 (12 HMMA) ----
            float accE[2][4];
            #pragma unroll
            for (int nt = 0; nt < 2; nt++)
                #pragma unroll
                for (int q = 0; q < 4; q++) accE[nt][q] = 0.f;
            #pragma unroll
            for (int s = 0; s < 2; s++) {
                uint32_t Ah[4], Al[4];
                split2(make_float2(accD[2 * s][0],     accD[2 * s][1]),     Ah[0], Al[0]);
                split2(make_float2(accD[2 * s][2],     accD[2 * s][3]),     Ah[1], Al[1]);
                split2(make_float2(accD[2 * s + 1][0], accD[2 * s + 1][1]), Ah[2], Al[2]);
                split2(make_float2(accD[2 * s + 1][2], accD[2 * s + 1][3]), Ah[3], Al[3]);
                #pragma unroll
                for (int nt = 0; nt < 2; nt++) {
                    MMA_BF16(accE[nt], Ah[0], Ah[1], Ah[2], Ah[3], B2h[s][nt][0], B2h[s][nt][1]);
                    MMA_BF16(accE[nt], Ah[0], Ah[1], Ah[2], Ah[3], B2l[s][nt][0], B2l[s][nt][1]);
                    MMA_BF16(accE[nt], Al[0], Al[1], Al[2], Al[3], B2h[s][nt][0], B2h[s][nt][1]);
                }
            }
            #pragma unroll
            for (int nt = 0; nt < 2; nt++) {
                float2 bb = nt ? b2v1 : b2v0;
                accE[nt][0] = fmaxf(accE[nt][0] + bb.x, 0.f);
                accE[nt][1] = fmaxf(accE[nt][1] + bb.y, 0.f);
                accE[nt][2] = fmaxf(accE[nt][2] + bb.x, 0.f);
                accE[nt][3] = fmaxf(accE[nt][3] + bb.y, 0.f);
            }

            // ---- layer 3 (3 HMMA) ----
            float accF[4] = {0.f, 0.f, 0.f, 0.f};
            {
                uint32_t Ah[4], Al[4];
                split2(make_float2(accE[0][0], accE[0][1]), Ah[0], Al[0]);
                split2(make_float2(accE[0][2], accE[0][3]), Ah[1], Al[1]);
                split2(make_float2(accE[1][0], accE[1][1]), Ah[2], Al[2]);
                split2(make_float2(accE[1][2], accE[1][3]), Ah[3], Al[3]);
                MMA_BF16(accF, Ah[0], Ah[1], Ah[2], Ah[3], B3h[0], B3h[1]);
                MMA_BF16(accF, Ah[0], Ah[1], Ah[2], Ah[3], B3l[0], B3l[1]);
                MMA_BF16(accF, Al[0], Al[1], Al[2], Al[3], B3h[0], B3h[1]);
            }

            // ---- layer 4 + mask + online softmax ----
            float p0 = fmaxf(accF[0] + b3v.x, 0.f) * w4v.x + fmaxf(accF[1] + b3v.y, 0.f) * w4v.y;
            float p1 = fmaxf(accF[2] + b3v.x, 0.f) * w4v.x + fmaxf(accF[3] + b3v.y, 0.f) * w4v.y;
            p0 += __shfl_xor_sync(0xffffffffu, p0, 1);
            p1 += __shfl_xor_sync(0xffffffffu, p1, 1);
            p0 += __shfl_xor_sync(0xffffffffu, p0, 2);
            p1 += __shfl_xor_sync(0xffffffffu, p1, 2);

            if (c == 0) {
                float sc0 = mv0 ? (p0 + vb4) : FLT_NEG;
                float sc1 = mv1 ? (p1 + vb4) : FLT_NEG;
                out[r0] = sc0;
                out[r1] = sc1;
                float mn = fmaxf(osm_m, fmaxf(sc0, sc1));
                osm_s = osm_s * __expf(osm_m - mn) + __expf(sc0 - mn) + __expf(sc1 - mn);
                osm_m = mn;
            }
        }
    }

    // ---- reduce (m,s) warp -> CTA ----
    #pragma unroll
    for (int o = 16; o; o >>= 1) {
        float m2 = __shfl_xor_sync(0xffffffffu, osm_m, o);
        float s2 = __shfl_xor_sync(0xffffffffu, osm_s, o);
        osm_combine(osm_m, osm_s, m2, s2);
    }
    if (lane == 0) { wm[wid] = osm_m; ws[wid] = osm_s; }
    __syncthreads();
    if (tid == 0) {
        float m = wm[0], s = ws[0];
        osm_combine(m, s, wm[1], ws[1]);
        osm_combine(m, s, wm[2], ws[2]);
        osm_combine(m, s, wm[3], ws[3]);
        g_cta_m[blockIdx.x] = m;
        g_cta_s[blockIdx.x] = s;
    }
}

// =================== finalize (merge folded in) ===================
__global__ __launch_bounds__(256)
void fin_kernel(float4* __restrict__ out4, int n4, int nctas) {
    __shared__ float sred[64];
    __shared__ float s_mx, s_inv;
    int tid = threadIdx.x;
    {
        float m = FLT_NEG, s = 0.f;
        for (int i = tid; i < nctas; i += 256)
            osm_combine(m, s, g_cta_m[i], g_cta_s[i]);
        #pragma unroll
        for (int o = 16; o; o >>= 1) {
            float m2 = __shfl_xor_sync(0xffffffffu, m, o);
            float s2 = __shfl_xor_sync(0xffffffffu, s, o);
            osm_combine(m, s, m2, s2);
        }
        if ((tid & 31) == 0) { sred[tid >> 5] = m; sred[8 + (tid >> 5)] = s; }
        __syncthreads();
        if (tid == 0) {
            float mm = sred[0], ss = sred[8];
            #pragma unroll
            for (int w = 1; w < 8; w++) osm_combine(mm, ss, sred[w], sred[8 + w]);
            s_mx = mm;
            s_inv = 1.0f / ss;
        }
        __syncthreads();
    }
    float inv = s_inv, mx = s_mx;
    for (int i = blockIdx.x * blockDim.x + tid; i < n4; i += gridDim.x * blockDim.x) {
        float4 v = out4[i];
        v.x = __expf(v.x - mx) * inv;
        v.y = __expf(v.y - mx) * inv;
        v.z = __expf(v.z - mx) * inv;
        v.w = __expf(v.w - mx) * inv;
        out4[i] = v;
    }
}

// =================== launch ===================
extern "C" void kernel_launch(void* const* d_in, const int* in_sizes, int n_in,
                              void* d_out, int out_size) {
    const float* x        = (const float*)d_in[0];
    const float* emb      = (const float*)d_in[1];
    const float* dag_sum  = (const float*)d_in[2];
    const float* glob_sum = (const float*)d_in[3];
    const void*  cnt_dag  = d_in[4];
    const void*  cnt_obs  = d_in[5];
    const void*  mask     = d_in[6];
    const float* W1 = (const float*)d_in[7];
    const float* b1 = (const float*)d_in[8];
    const float* W2 = (const float*)d_in[9];
    const float* b2 = (const float*)d_in[10];
    const float* W3 = (const float*)d_in[11];
    const float* b3 = (const float*)d_in[12];
    const float* W4 = (const float*)d_in[13];
    const float* b4 = (const float*)d_in[14];
    float* out = (float*)d_out;

    static int grid_main = 0;
    if (grid_main == 0) {
        int nb = 1, nsm = 148;
        cudaOccupancyMaxActiveBlocksPerMultiprocessor(&nb, main_kernel, 128, 0);
        cudaDeviceGetAttribute(&nsm, cudaDevAttrMultiProcessorCount, 0);
        if (nb < 1) nb = 1;
        grid_main = nb * nsm;
        if (grid_main > 1024) grid_main = 1024;
        if (grid_main > N_TILES) grid_main = N_TILES;
    }

    prep_kernel<<<660, 1024>>>(cnt_dag, cnt_obs, dag_sum, glob_sum, W1, b1,
                               (const unsigned char*)mask);
    segid_kernel<<<(N_NODES / 4 + 255) / 256, 256>>>();
    main_kernel<<<grid_main, 128>>>(x, emb, mask, W1, W2, b2, W3, b3, W4, b4, out);
    fin_kernel<<<1024, 256>>>((float4*)out, N_NODES / 4, grid_main);
}